// round 8
// baseline (speedup 1.0000x reference)
#include <cuda_runtime.h>

#define NUM_NODES 100000
#define NUM_EDGES 6400000
#define NUM_STEPS 10

#define TILE 10000                 // dst nodes per tile (40KB smem acc in spmv)
#define NTILES 10
#define CTAS_PER_TILE 15           // 150 CTAs, ~1/SM (R5 proven config)
#define STEP_TPB 1024

#define SRC_SHIFT 11               // src group = src >> 11 (2048-node / 8KB window)
#define NSRCG 49                   // ceil(100000 / 2048)
#define NBINS (NTILES * NSRCG)     // 490 bins, key = tile*NSRCG + (src>>11)

#define STAGE_CAP 8                // records per bin stage (64B chunks)
#define SCAT_TPB 256
#define SCAT_GRID 148

// Scratch (allocation-free rule: __device__ globals)
__device__ __align__(16) uint2 g_sp2[NUM_EDGES];  // {packed, prob-bits}, bin-grouped
__device__ int   g_bins[NBINS];
__device__ int   g_binptr[NBINS + 1];
__device__ int   g_cursor[NBINS];
__device__ float g_curA[NUM_NODES];
__device__ float g_curB[NUM_NODES];
__device__ float g_surv[NUM_NODES];
__device__ float g_acc[NUM_NODES];
__device__ int   g_is64;

// ---------------------------------------------------------------------------
// Fused prep: detect int64-vs-int32 (block 0), zero bin histogram, init nodes.
// ---------------------------------------------------------------------------
__global__ void prep_kernel(const int* __restrict__ w, const float* __restrict__ x) {
    int i = blockIdx.x * blockDim.x + threadIdx.x;
    if (blockIdx.x == 0) {
        __shared__ int nz;
        if (threadIdx.x == 0) nz = 0;
        __syncthreads();
        for (int k = threadIdx.x; k < 4096; k += blockDim.x)
            if (w[2 * k + 1] != 0) nz = 1;
        __syncthreads();
        if (threadIdx.x == 0) g_is64 = nz ? 0 : 1;
    }
    if (i < NBINS) g_bins[i] = 0;
    if (i < NUM_NODES) {
        float xv = x[i];
        g_curA[i] = xv;
        g_surv[i] = 1.0f - xv;
        g_acc[i]  = 0.0f;
    }
}

// ---------------------------------------------------------------------------
// Decode edge i -> (src, dst) handling either index width.
// ---------------------------------------------------------------------------
__device__ __forceinline__ void load_edge(const void* eidx, int i, int is64,
                                          int& s, int& d) {
    if (is64) {
        const long long* e = (const long long*)eidx;
        s = (int)e[i];
        d = (int)e[NUM_EDGES + i];
    } else {
        const int* e = (const int*)eidx;
        s = e[i];
        d = e[NUM_EDGES + i];
    }
    s = min(max(s, 0), NUM_NODES - 1);
    d = min(max(d, 0), NUM_NODES - 1);
}

__device__ __forceinline__ int edge_bin(int s, int d) {
    return (d / TILE) * NSRCG + (s >> SRC_SHIFT);
}

// ---------------------------------------------------------------------------
// Histogram of 490 bins via smem (one partial hist per CTA, flushed once).
// ---------------------------------------------------------------------------
__global__ void hist_kernel(const void* __restrict__ eidx) {
    __shared__ int h[NBINS];
    for (int b = threadIdx.x; b < NBINS; b += blockDim.x) h[b] = 0;
    __syncthreads();
    int is64 = g_is64;
    int per = (NUM_EDGES + gridDim.x - 1) / gridDim.x;
    int a = blockIdx.x * per;
    int b = min(a + per, NUM_EDGES);
    for (int i = a + threadIdx.x; i < b; i += blockDim.x) {
        int s, d;
        load_edge(eidx, i, is64, s, d);
        atomicAdd(&h[edge_bin(s, d)], 1);
    }
    __syncthreads();
    for (int k = threadIdx.x; k < NBINS; k += blockDim.x)
        if (h[k]) atomicAdd(&g_bins[k], h[k]);
}

// ---------------------------------------------------------------------------
// Tiny exclusive scan over 490 bins (single CTA) -> binptr + cursors.
// ---------------------------------------------------------------------------
__global__ void scan_kernel() {
    __shared__ int s[512];
    int tid = threadIdx.x;
    int v = (tid < NBINS) ? g_bins[tid] : 0;
    s[tid] = v;
    __syncthreads();
    #pragma unroll
    for (int o = 1; o < 512; o <<= 1) {
        int t = (tid >= o) ? s[tid - o] : 0;
        __syncthreads();
        s[tid] += t;
        __syncthreads();
    }
    if (tid < NBINS) {
        int r = s[tid] - v;    // exclusive
        g_binptr[tid] = r;
        g_cursor[tid] = r;
    }
    if (tid == 0) g_binptr[NBINS] = NUM_EDGES;
}

// ---------------------------------------------------------------------------
// Staged scatter: smem-stage 8 records per bin, flush full 64B chunks with one
// cursor atomic each; overflow (slot>=CAP) and final partial bins spill as
// individual writes (rare). Output: g_sp2 grouped by bin.
// packed = src << 14 | dst_local   (src < 2^17, dst_local < 10000 < 2^14)
// ---------------------------------------------------------------------------
__global__ void __launch_bounds__(SCAT_TPB)
scatter_staged_kernel(const void* __restrict__ eidx,
                      const float* __restrict__ probs) {
    __shared__ uint2 stage[NBINS][STAGE_CAP];   // 490*8*8B = 30.6KB
    __shared__ int   cnt[NBINS];

    for (int k = threadIdx.x; k < NBINS; k += SCAT_TPB) cnt[k] = 0;
    __syncthreads();

    int is64 = g_is64;
    int per = (NUM_EDGES + gridDim.x - 1) / gridDim.x;
    int a = blockIdx.x * per;
    int b = min(a + per, NUM_EDGES);

    for (int base = a; base < b; base += SCAT_TPB) {
        int i = base + threadIdx.x;
        if (i < b) {
            int s, d;
            load_edge(eidx, i, is64, s, d);
            int tile = d / TILE;
            int dl   = d - tile * TILE;
            int bin  = tile * NSRCG + (s >> SRC_SHIFT);
            uint2 rec = make_uint2((unsigned)((s << 14) | dl),
                                   (unsigned)__float_as_int(probs[i]));
            int slot = atomicAdd(&cnt[bin], 1);
            if (slot < STAGE_CAP) {
                stage[bin][slot] = rec;
            } else {
                // overflow: direct (rare) global spill
                int pos = atomicAdd(&g_cursor[bin], 1);
                g_sp2[pos] = rec;
            }
        }
        __syncthreads();
        // flush bins with a full stage
        for (int k = threadIdx.x; k < NBINS; k += SCAT_TPB) {
            int c = cnt[k];
            if (c >= STAGE_CAP) {
                int pos = atomicAdd(&g_cursor[k], STAGE_CAP);
                #pragma unroll
                for (int r = 0; r < STAGE_CAP; r++)
                    g_sp2[pos + r] = stage[k][r];
                cnt[k] = 0;
            }
        }
        __syncthreads();
    }

    // drain partial bins
    for (int k = threadIdx.x; k < NBINS; k += SCAT_TPB) {
        int c = cnt[k];
        if (c > 0) {
            int pos = atomicAdd(&g_cursor[k], c);
            for (int r = 0; r < c; r++)
                g_sp2[pos + r] = stage[k][r];
        }
    }
}

// ---------------------------------------------------------------------------
// Per-step edge pass (R5-proven): one dst tile per CTA group, smem accumulate.
// srcs are grouped in 8KB windows -> gather L1/L2 resident.
// ---------------------------------------------------------------------------
__global__ void __launch_bounds__(STEP_TPB)
spmv_tile_kernel(int step) {
    __shared__ float acc[TILE];
    int tile = blockIdx.x / CTAS_PER_TILE;
    int sub  = blockIdx.x % CTAS_PER_TILE;

    for (int i = threadIdx.x; i < TILE; i += STEP_TPB) acc[i] = 0.0f;
    __syncthreads();

    const float* cur = (step & 1) ? g_curB : g_curA;

    int start = g_binptr[tile * NSRCG];
    int end   = g_binptr[(tile + 1) * NSRCG];
    int n = end - start;
    int per = (n + CTAS_PER_TILE - 1) / CTAS_PER_TILE;
    int a = start + sub * per;
    int b = min(a + per, end);

    for (int j = a + threadIdx.x; j < b; j += STEP_TPB) {
        uint2 e = g_sp2[j];
        int src = (int)(e.x >> 14);
        int dl  = (int)(e.x & 16383u);
        atomicAdd(&acc[dl], __ldg(&cur[src]) * __int_as_float((int)e.y));
    }
    __syncthreads();

    int base = tile * TILE;
    for (int i = threadIdx.x; i < TILE; i += STEP_TPB) {
        float v = acc[i];
        if (v != 0.0f) atomicAdd(&g_acc[base + i], v);
    }
}

// ---------------------------------------------------------------------------
// Per-step node pass: cur' = scale*acc + bias; surv *= (1-cur'); acc = 0.
// Buffer parity resolved in device code (host &symbol is invalid).
// ---------------------------------------------------------------------------
__global__ void node_kernel(const float* __restrict__ td,
                            const float* __restrict__ ew,
                            const float* __restrict__ nb,
                            int step, int is_last,
                            float* __restrict__ out) {
    int n = blockIdx.x * blockDim.x + threadIdx.x;
    if (n >= NUM_NODES) return;

    float* curn = (step & 1) ? g_curA : g_curB;

    float tdv = td[step];
    float scale = ew[step] * expf(-(tdv * tdv));
    float c = scale * g_acc[n] + nb[0];
    g_acc[n] = 0.0f;
    curn[n] = c;
    float sv = g_surv[n] * (1.0f - c);
    g_surv[n] = sv;
    if (is_last) {
        float fi = 1.0f - sv;
        out[n] = fminf(fmaxf(fi, 0.0f), 1.0f);
    }
}

// ---------------------------------------------------------------------------
// Launch
// ---------------------------------------------------------------------------
extern "C" void kernel_launch(void* const* d_in, const int* in_sizes, int n_in,
                              void* d_out, int out_size) {
    const float* x     = (const float*)d_in[0];
    const void*  eidx  = d_in[1];
    const float* probs = (const float*)d_in[2];
    const float* td    = (const float*)d_in[3];
    const float* nb    = (const float*)d_in[4];
    const float* ew    = (const float*)d_in[5];
    float*       out   = (float*)d_out;

    const int TB = 256;
    int pblocks = (NUM_NODES + TB - 1) / TB;     // covers NBINS too

    prep_kernel<<<pblocks, TB>>>((const int*)eidx, x);
    hist_kernel<<<SCAT_GRID, SCAT_TPB>>>(eidx);
    scan_kernel<<<1, 512>>>();
    scatter_staged_kernel<<<SCAT_GRID, SCAT_TPB>>>(eidx, probs);

    for (int step = 0; step < NUM_STEPS; step++) {
        spmv_tile_kernel<<<NTILES * CTAS_PER_TILE, STEP_TPB>>>(step);
        node_kernel<<<pblocks, TB>>>(td, ew, nb, step,
                                     (step == NUM_STEPS - 1) ? 1 : 0, out);
    }
}

// round 9
// speedup vs baseline: 1.3294x; 1.3294x over previous
#include <cuda_runtime.h>

#define NUM_NODES 100000
#define NUM_EDGES 6400000
#define NUM_STEPS 10

#define TILE 10000                 // dst nodes per tile (40KB smem acc in spmv)
#define NTILES 10
#define CTAS_PER_TILE 15           // 150 CTAs (R5-proven)
#define STEP_TPB 1024

#define SRC_SHIFT 5                // src group = src >> 5 (32-node / 128B window)
#define NSRCG 3125                 // 100000 / 32
#define NBINS (NTILES * NSRCG)     // 31,250 bins: key = tile*NSRCG + (src>>5)
#define RANK_BITS 17               // bin<<17 | rank  (rank max ~285 << 131072)

// Scratch (allocation-free rule: __device__ globals)
__device__ int2  g_edges[NUM_EDGES];              // {bin<<17|rank, src<<14|dl}
__device__ __align__(16) uint2 g_sp2[NUM_EDGES];  // {packed, prob-bits}, bin-grouped
__device__ int   g_bins[NBINS];
__device__ int   g_binptr[NBINS + 1];
__device__ float g_curA[NUM_NODES];
__device__ float g_curB[NUM_NODES];
__device__ float g_surv[NUM_NODES];
__device__ float g_acc[NUM_NODES];
__device__ int   g_is64;

// ---------------------------------------------------------------------------
// Fused prep: detect int64-vs-int32 (block 0), zero bins, init node state.
// ---------------------------------------------------------------------------
__global__ void prep_kernel(const int* __restrict__ w, const float* __restrict__ x) {
    int i = blockIdx.x * blockDim.x + threadIdx.x;
    if (blockIdx.x == 0) {
        __shared__ int nz;
        if (threadIdx.x == 0) nz = 0;
        __syncthreads();
        for (int k = threadIdx.x; k < 4096; k += blockDim.x)
            if (w[2 * k + 1] != 0) nz = 1;
        __syncthreads();
        if (threadIdx.x == 0) g_is64 = nz ? 0 : 1;
    }
    if (i < NBINS) g_bins[i] = 0;
    if (i < NUM_NODES) {
        float xv = x[i];
        g_curA[i] = xv;
        g_surv[i] = 1.0f - xv;
        g_acc[i]  = 0.0f;
    }
}

// ---------------------------------------------------------------------------
// Convert + histogram + rank: the hist atomic's return value IS the edge's
// permanent within-bin rank -> scatter needs no atomics at all.
// ---------------------------------------------------------------------------
__global__ void convert_hist_kernel(const void* __restrict__ eidx) {
    int i = blockIdx.x * blockDim.x + threadIdx.x;
    if (i >= NUM_EDGES) return;
    int s, d;
    if (g_is64) {
        const long long* e = (const long long*)eidx;
        s = (int)e[i];
        d = (int)e[NUM_EDGES + i];
    } else {
        const int* e = (const int*)eidx;
        s = e[i];
        d = e[NUM_EDGES + i];
    }
    s = min(max(s, 0), NUM_NODES - 1);
    d = min(max(d, 0), NUM_NODES - 1);
    int tile = d / TILE;
    int dl   = d - tile * TILE;
    int bin  = tile * NSRCG + (s >> SRC_SHIFT);
    int rank = atomicAdd(&g_bins[bin], 1);
    rank &= (1 << RANK_BITS) - 1;               // defensive
    g_edges[i] = make_int2((bin << RANK_BITS) | rank, (s << 14) | dl);
}

// ---------------------------------------------------------------------------
// Single-CTA chunked exclusive scan over 31,250 bins (serial carry).
// ---------------------------------------------------------------------------
#define SCAN_TPB 1024
__global__ void scan_kernel() {
    __shared__ int s[SCAN_TPB];
    __shared__ int carry;
    int tid = threadIdx.x;
    if (tid == 0) carry = 0;
    __syncthreads();

    const int nchunks = (NBINS + SCAN_TPB - 1) / SCAN_TPB;   // 31
    for (int c = 0; c < nchunks; c++) {
        int i = c * SCAN_TPB + tid;
        int v = (i < NBINS) ? g_bins[i] : 0;
        s[tid] = v;
        __syncthreads();
        #pragma unroll
        for (int o = 1; o < SCAN_TPB; o <<= 1) {
            int t = (tid >= o) ? s[tid - o] : 0;
            __syncthreads();
            s[tid] += t;
            __syncthreads();
        }
        int excl = carry + s[tid] - v;          // reads carry before update
        if (i < NBINS) g_binptr[i] = excl;
        int total = s[SCAN_TPB - 1];
        __syncthreads();
        if (tid == 0) carry += total;
        __syncthreads();
    }
    if (tid == 0) g_binptr[NBINS] = NUM_EDGES;
}

// ---------------------------------------------------------------------------
// Atomic-free scatter: pos = binptr[bin] + rank. Pure streaming + one random
// 8B write per edge.
// ---------------------------------------------------------------------------
__global__ void scatter_kernel(const float* __restrict__ probs) {
    int i = blockIdx.x * blockDim.x + threadIdx.x;
    if (i >= NUM_EDGES) return;
    int2 e = g_edges[i];
    int bin  = ((unsigned)e.x) >> RANK_BITS;
    int rank = e.x & ((1 << RANK_BITS) - 1);
    int pos  = g_binptr[bin] + rank;
    g_sp2[pos] = make_uint2((unsigned)e.y, (unsigned)__float_as_int(probs[i]));
}

// ---------------------------------------------------------------------------
// Per-step edge pass (R5-proven, verbatim): one dst tile per CTA group,
// smem accumulation; src 128B-window locality keeps gathers L1-resident.
// ---------------------------------------------------------------------------
__global__ void __launch_bounds__(STEP_TPB)
spmv_tile_kernel(int step) {
    __shared__ float acc[TILE];
    int tile = blockIdx.x / CTAS_PER_TILE;
    int sub  = blockIdx.x % CTAS_PER_TILE;

    for (int i = threadIdx.x; i < TILE; i += STEP_TPB) acc[i] = 0.0f;
    __syncthreads();

    const float* cur = (step & 1) ? g_curB : g_curA;

    int start = g_binptr[tile * NSRCG];
    int end   = g_binptr[(tile + 1) * NSRCG];
    int n = end - start;
    int per = (n + CTAS_PER_TILE - 1) / CTAS_PER_TILE;
    int a = start + sub * per;
    int b = min(a + per, end);

    for (int j = a + threadIdx.x; j < b; j += STEP_TPB) {
        uint2 e = g_sp2[j];
        int src = (int)(e.x >> 14);
        int dl  = (int)(e.x & 16383u);
        atomicAdd(&acc[dl], __ldg(&cur[src]) * __int_as_float((int)e.y));
    }
    __syncthreads();

    int base = tile * TILE;
    for (int i = threadIdx.x; i < TILE; i += STEP_TPB) {
        float v = acc[i];
        if (v != 0.0f) atomicAdd(&g_acc[base + i], v);
    }
}

// ---------------------------------------------------------------------------
// Per-step node pass: cur' = scale*acc + bias; surv *= (1-cur'); acc = 0.
// Buffer parity resolved in device code (host &symbol is invalid).
// ---------------------------------------------------------------------------
__global__ void node_kernel(const float* __restrict__ td,
                            const float* __restrict__ ew,
                            const float* __restrict__ nb,
                            int step, int is_last,
                            float* __restrict__ out) {
    int n = blockIdx.x * blockDim.x + threadIdx.x;
    if (n >= NUM_NODES) return;

    float* curn = (step & 1) ? g_curA : g_curB;

    float tdv = td[step];
    float scale = ew[step] * expf(-(tdv * tdv));
    float c = scale * g_acc[n] + nb[0];
    g_acc[n] = 0.0f;
    curn[n] = c;
    float sv = g_surv[n] * (1.0f - c);
    g_surv[n] = sv;
    if (is_last) {
        float fi = 1.0f - sv;
        out[n] = fminf(fmaxf(fi, 0.0f), 1.0f);
    }
}

// ---------------------------------------------------------------------------
// Launch
// ---------------------------------------------------------------------------
extern "C" void kernel_launch(void* const* d_in, const int* in_sizes, int n_in,
                              void* d_out, int out_size) {
    const float* x     = (const float*)d_in[0];
    const void*  eidx  = d_in[1];
    const float* probs = (const float*)d_in[2];
    const float* td    = (const float*)d_in[3];
    const float* nb    = (const float*)d_in[4];
    const float* ew    = (const float*)d_in[5];
    float*       out   = (float*)d_out;

    const int TB = 256;
    int eblocks = (NUM_EDGES + TB - 1) / TB;
    int pblocks = (NUM_NODES + TB - 1) / TB;     // covers NBINS too

    prep_kernel<<<pblocks, TB>>>((const int*)eidx, x);
    convert_hist_kernel<<<eblocks, TB>>>(eidx);
    scan_kernel<<<1, SCAN_TPB>>>();
    scatter_kernel<<<eblocks, TB>>>(probs);

    for (int step = 0; step < NUM_STEPS; step++) {
        spmv_tile_kernel<<<NTILES * CTAS_PER_TILE, STEP_TPB>>>(step);
        node_kernel<<<pblocks, TB>>>(td, ew, nb, step,
                                     (step == NUM_STEPS - 1) ? 1 : 0, out);
    }
}

// round 10
// speedup vs baseline: 1.4665x; 1.1031x over previous
#include <cuda_runtime.h>

#define NUM_NODES 100000
#define NUM_EDGES 6400000
#define NUM_STEPS 10

#define TILE 10000                 // dst nodes per tile (40KB smem acc in spmv)
#define NTILES 10
#define CTAS_PER_TILE 15           // 150 CTAs (R5-proven)
#define STEP_TPB 1024

#define NBINS (NTILES * NUM_NODES) // 1M bins: key = dst_tile*N + src (exact src)
#define RANK_BITS 12               // packed key = bin<<12 | rank (rank << 4096)
#define SCAN_BLK 1024
#define NSB ((NBINS + SCAN_BLK - 1) / SCAN_BLK)   // 977

// Scratch (allocation-free rule: __device__ globals)
__device__ uint2 g_edges[NUM_EDGES];              // {bin<<12|rank, src<<14|dl}
__device__ __align__(16) uint2 g_sp2[NUM_EDGES];  // {packed, prob-bits}, sorted
__device__ int   g_bins[NBINS];
__device__ int   g_binptr[NBINS + 1];
__device__ int   g_blocksum[NSB];
__device__ float g_curA[NUM_NODES];
__device__ float g_curB[NUM_NODES];
__device__ float g_surv[NUM_NODES];
__device__ float g_acc[NUM_NODES];
__device__ int   g_is64;

// ---------------------------------------------------------------------------
// Fused prep: detect int64-vs-int32 (block 0), zero bins, init node state.
// ---------------------------------------------------------------------------
__global__ void prep_kernel(const int* __restrict__ w, const float* __restrict__ x) {
    int i = blockIdx.x * blockDim.x + threadIdx.x;
    if (blockIdx.x == 0) {
        __shared__ int nz;
        if (threadIdx.x == 0) nz = 0;
        __syncthreads();
        for (int k = threadIdx.x; k < 4096; k += blockDim.x)
            if (w[2 * k + 1] != 0) nz = 1;
        __syncthreads();
        if (threadIdx.x == 0) g_is64 = nz ? 0 : 1;
    }
    if (i < NBINS) g_bins[i] = 0;
    if (i < NUM_NODES) {
        float xv = x[i];
        g_curA[i] = xv;
        g_surv[i] = 1.0f - xv;
        g_acc[i]  = 0.0f;
    }
}

// ---------------------------------------------------------------------------
// Convert + histogram + rank: hist atomic's return value IS the edge's
// permanent within-bin rank -> scatter needs no atomics.
// bin = dst_tile * NUM_NODES + src ; payload = src<<14 | dst_local
// ---------------------------------------------------------------------------
__global__ void convert_hist_kernel(const void* __restrict__ eidx) {
    int i = blockIdx.x * blockDim.x + threadIdx.x;
    if (i >= NUM_EDGES) return;
    int s, d;
    if (g_is64) {
        const long long* e = (const long long*)eidx;
        s = (int)e[i];
        d = (int)e[NUM_EDGES + i];
    } else {
        const int* e = (const int*)eidx;
        s = e[i];
        d = e[NUM_EDGES + i];
    }
    s = min(max(s, 0), NUM_NODES - 1);
    d = min(max(d, 0), NUM_NODES - 1);
    int tile = d / TILE;
    int dl   = d - tile * TILE;
    int bin  = tile * NUM_NODES + s;
    unsigned rank = (unsigned)atomicAdd(&g_bins[bin], 1) & ((1u << RANK_BITS) - 1u);
    g_edges[i] = make_uint2(((unsigned)bin << RANK_BITS) | rank,
                            (unsigned)((s << 14) | dl));
}

// ---------------------------------------------------------------------------
// 3-phase exclusive scan of g_bins -> g_binptr (R5-proven).
// ---------------------------------------------------------------------------
__global__ void scan1_kernel() {
    __shared__ int s[SCAN_BLK];
    int tid = threadIdx.x;
    int i = blockIdx.x * SCAN_BLK + tid;
    int v = (i < NBINS) ? g_bins[i] : 0;
    s[tid] = v;
    __syncthreads();
    #pragma unroll
    for (int o = 1; o < SCAN_BLK; o <<= 1) {
        int t = (tid >= o) ? s[tid - o] : 0;
        __syncthreads();
        s[tid] += t;
        __syncthreads();
    }
    if (i < NBINS) g_binptr[i] = s[tid] - v;   // exclusive, sans block offset
    if (tid == SCAN_BLK - 1) g_blocksum[blockIdx.x] = s[tid];
}

__global__ void scan2_kernel() {
    __shared__ int s[SCAN_BLK];
    int tid = threadIdx.x;
    int v = (tid < NSB) ? g_blocksum[tid] : 0;
    s[tid] = v;
    __syncthreads();
    #pragma unroll
    for (int o = 1; o < SCAN_BLK; o <<= 1) {
        int t = (tid >= o) ? s[tid - o] : 0;
        __syncthreads();
        s[tid] += t;
        __syncthreads();
    }
    if (tid < NSB) g_blocksum[tid] = s[tid] - v;  // exclusive block offsets
    if (tid == 0) g_binptr[NBINS] = NUM_EDGES;
}

__global__ void scan3_kernel() {
    int i = blockIdx.x * blockDim.x + threadIdx.x;
    if (i >= NBINS) return;
    g_binptr[i] += g_blocksum[i / SCAN_BLK];
}

// ---------------------------------------------------------------------------
// Atomic-free scatter: pos = binptr[bin] + rank.
// ---------------------------------------------------------------------------
__global__ void scatter_kernel(const float* __restrict__ probs) {
    int i = blockIdx.x * blockDim.x + threadIdx.x;
    if (i >= NUM_EDGES) return;
    uint2 e = g_edges[i];
    int bin  = (int)(e.x >> RANK_BITS);
    int rank = (int)(e.x & ((1u << RANK_BITS) - 1u));
    int pos  = g_binptr[bin] + rank;
    g_sp2[pos] = make_uint2(e.y, (unsigned)__float_as_int(probs[i]));
}

// ---------------------------------------------------------------------------
// Per-step edge pass (R5-proven verbatim): one dst tile per CTA group,
// smem accumulation; exact-src ordering -> streaming/broadcast gathers.
// ---------------------------------------------------------------------------
__global__ void __launch_bounds__(STEP_TPB)
spmv_tile_kernel(int step) {
    __shared__ float acc[TILE];
    int tile = blockIdx.x / CTAS_PER_TILE;
    int sub  = blockIdx.x % CTAS_PER_TILE;

    for (int i = threadIdx.x; i < TILE; i += STEP_TPB) acc[i] = 0.0f;
    __syncthreads();

    const float* cur = (step & 1) ? g_curB : g_curA;

    int start = g_binptr[tile * NUM_NODES];
    int end   = g_binptr[(tile + 1) * NUM_NODES];
    int n = end - start;
    int per = (n + CTAS_PER_TILE - 1) / CTAS_PER_TILE;
    int a = start + sub * per;
    int b = min(a + per, end);

    for (int j = a + threadIdx.x; j < b; j += STEP_TPB) {
        uint2 e = g_sp2[j];
        int src = (int)(e.x >> 14);
        int dl  = (int)(e.x & 16383u);
        atomicAdd(&acc[dl], __ldg(&cur[src]) * __int_as_float((int)e.y));
    }
    __syncthreads();

    int base = tile * TILE;
    for (int i = threadIdx.x; i < TILE; i += STEP_TPB) {
        float v = acc[i];
        if (v != 0.0f) atomicAdd(&g_acc[base + i], v);
    }
}

// ---------------------------------------------------------------------------
// Per-step node pass: cur' = scale*acc + bias; surv *= (1-cur'); acc = 0.
// Buffer parity resolved in device code (host &symbol is invalid).
// ---------------------------------------------------------------------------
__global__ void node_kernel(const float* __restrict__ td,
                            const float* __restrict__ ew,
                            const float* __restrict__ nb,
                            int step, int is_last,
                            float* __restrict__ out) {
    int n = blockIdx.x * blockDim.x + threadIdx.x;
    if (n >= NUM_NODES) return;

    float* curn = (step & 1) ? g_curA : g_curB;

    float tdv = td[step];
    float scale = ew[step] * expf(-(tdv * tdv));
    float c = scale * g_acc[n] + nb[0];
    g_acc[n] = 0.0f;
    curn[n] = c;
    float sv = g_surv[n] * (1.0f - c);
    g_surv[n] = sv;
    if (is_last) {
        float fi = 1.0f - sv;
        out[n] = fminf(fmaxf(fi, 0.0f), 1.0f);
    }
}

// ---------------------------------------------------------------------------
// Launch
// ---------------------------------------------------------------------------
extern "C" void kernel_launch(void* const* d_in, const int* in_sizes, int n_in,
                              void* d_out, int out_size) {
    const float* x     = (const float*)d_in[0];
    const void*  eidx  = d_in[1];
    const float* probs = (const float*)d_in[2];
    const float* td    = (const float*)d_in[3];
    const float* nb    = (const float*)d_in[4];
    const float* ew    = (const float*)d_in[5];
    float*       out   = (float*)d_out;

    const int TB = 256;
    int eblocks = (NUM_EDGES + TB - 1) / TB;
    int bblocks = (NBINS + TB - 1) / TB;

    prep_kernel<<<bblocks, TB>>>((const int*)eidx, x);
    convert_hist_kernel<<<eblocks, TB>>>(eidx);
    scan1_kernel<<<NSB, SCAN_BLK>>>();
    scan2_kernel<<<1, SCAN_BLK>>>();
    scan3_kernel<<<bblocks, TB>>>();
    scatter_kernel<<<eblocks, TB>>>(probs);

    int nblocks = (NUM_NODES + TB - 1) / TB;
    for (int step = 0; step < NUM_STEPS; step++) {
        spmv_tile_kernel<<<NTILES * CTAS_PER_TILE, STEP_TPB>>>(step);
        node_kernel<<<nblocks, TB>>>(td, ew, nb, step,
                                     (step == NUM_STEPS - 1) ? 1 : 0, out);
    }
}